// round 4
// baseline (speedup 1.0000x reference)
#include <cuda_runtime.h>

#define PI_F 3.14159265358979323846f

typedef unsigned long long u64;

static __device__ __forceinline__ float f_rsqrt(float x){ float r; asm("rsqrt.approx.f32 %0, %1;" : "=f"(r) : "f"(x)); return r; }
static __device__ __forceinline__ float f_sqrt (float x){ float r; asm("sqrt.approx.f32 %0, %1;"  : "=f"(r) : "f"(x)); return r; }
static __device__ __forceinline__ float f_rcp  (float x){ float r; asm("rcp.approx.f32 %0, %1;"   : "=f"(r) : "f"(x)); return r; }
static __device__ __forceinline__ float f_tanh (float x){ float r; asm("tanh.approx.f32 %0, %1;"  : "=f"(r) : "f"(x)); return r; }

// ---- packed f32x2 helpers (Blackwell FFMA2 path, PTX-only) ----------------
static __device__ __forceinline__ u64 ffma2(u64 a, u64 b, u64 c){
    u64 d; asm("fma.rn.f32x2 %0, %1, %2, %3;" : "=l"(d) : "l"(a), "l"(b), "l"(c)); return d;
}
static __device__ __forceinline__ u64 packf2(float lo, float hi){
    u64 v; asm("mov.b64 %0, {%1, %2};" : "=l"(v) : "f"(lo), "f"(hi)); return v;
}
static __device__ __forceinline__ float2 unpackf2(u64 v){
    float2 u; asm("mov.b64 {%0, %1}, %2;" : "=f"(u.x), "=f"(u.y) : "l"(v)); return u;
}
static __device__ __forceinline__ ulonglong2 ldcs_u64x2(const void* p){
    ulonglong2 v; asm("ld.global.cs.v2.u64 {%0, %1}, [%2];" : "=l"(v.x), "=l"(v.y) : "l"(p)); return v;
}
static __device__ __forceinline__ void stcs_u64x2(void* p, u64 a, u64 b){
    asm volatile("st.global.cs.v2.u64 [%0], {%1, %2};" :: "l"(p), "l"(a), "l"(b) : "memory");
}

struct c32 { float x, y; };
static __device__ __forceinline__ c32 cmul(c32 a, c32 b){
    c32 r;
    r.x = fmaf(a.x, b.x, -a.y * b.y);
    r.y = fmaf(a.x, b.y,  a.y * b.x);
    return r;
}

static __device__ __forceinline__ constexpr int cnotp(int j, int c, int tq){
    return j ^ (((j >> (3 - c)) & 1) << (3 - tq));
}

constexpr int THREADS = 256;
constexpr int BATCH   = 65536;
constexpr int BLOCKS  = BATCH / 32;    // 2048 one-shot blocks, 32 rows each

// ---------------------------------------------------------------------------
// full 4-qubit circuit for one row (per-lane registers)
// ---------------------------------------------------------------------------
static __device__ __forceinline__ float4 circuit(float f0, float f1, float f2, float f3,
                                                 const float2 (*rotm)[4])
{
    auto mkv = [](float fq, c32& v0, c32& v1) {
        float u  = f_sqrt(fmaf(fq, fq, 1.f));
        float ta = fq * f_rcp(1.f + u);
        float c1 = f_rsqrt(fmaf(ta, ta, 1.f));
        float s1 = ta * c1;
        float g  = fq * fq;
        float u2 = f_sqrt(fmaf(g, g, 1.f));
        float tb = g * f_rcp(1.f + u2);
        float cb = f_rsqrt(fmaf(tb, tb, 1.f));
        float sb = tb * cb;
        const float r2 = 0.7071067811865476f;
        float p = (c1 - s1) * r2;
        float q = (c1 + s1) * r2;
        v0.x = p * cb; v0.y = -p * sb;
        v1.x = q * cb; v1.y =  q * sb;
    };
    c32 va0, va1, vb0, vb1, vc0, vc1, vd0, vd1;
    mkv(f0, va0, va1); mkv(f1, vb0, vb1); mkv(f2, vc0, vc1); mkv(f3, vd0, vd1);

    c32 w01[4] = { cmul(va0, vb0), cmul(va0, vb1), cmul(va1, vb0), cmul(va1, vb1) };
    c32 w23[4] = { cmul(vc0, vd0), cmul(vc0, vd1), cmul(vc1, vd0), cmul(vc1, vd1) };
    c32 psi[16];
    #pragma unroll
    for (int j = 0; j < 16; j++) psi[j] = cmul(w01[j >> 2], w23[j & 3]);

    // CNOT ring (compile-time index permutations)
    {
        c32 tmp[16];
        #pragma unroll
        for (int j = 0; j < 16; j++) tmp[j] = psi[cnotp(j, 0, 1)];
        #pragma unroll
        for (int j = 0; j < 16; j++) psi[j] = tmp[j];
        #pragma unroll
        for (int j = 0; j < 16; j++) tmp[j] = psi[cnotp(j, 1, 2)];
        #pragma unroll
        for (int j = 0; j < 16; j++) psi[j] = tmp[j];
        #pragma unroll
        for (int j = 0; j < 16; j++) tmp[j] = psi[cnotp(j, 2, 3)];
        #pragma unroll
        for (int j = 0; j < 16; j++) psi[j] = tmp[j];
        #pragma unroll
        for (int j = 0; j < 16; j++) tmp[j] = psi[cnotp(j, 3, 0)];
        #pragma unroll
        for (int j = 0; j < 16; j++) psi[j] = tmp[j];
    }

    // Rot gates (constant matrices broadcast from smem)
    #pragma unroll
    for (int q = 0; q < 4; q++) {
        float2 m00 = rotm[q][0], m01 = rotm[q][1], m10 = rotm[q][2], m11 = rotm[q][3];
        c32 U00 = {m00.x, m00.y}, U01 = {m01.x, m01.y};
        c32 U10 = {m10.x, m10.y}, U11 = {m11.x, m11.y};
        const int mask = 8 >> q;
        #pragma unroll
        for (int j = 0; j < 16; j++) {
            if ((j & mask) == 0) {
                const int j1 = j | mask;
                c32 a = psi[j], b = psi[j1];
                c32 t0 = cmul(U00, a), t1 = cmul(U01, b);
                c32 t2 = cmul(U10, a), t3 = cmul(U11, b);
                psi[j].x  = t0.x + t1.x; psi[j].y  = t0.y + t1.y;
                psi[j1].x = t2.x + t3.x; psi[j1].y = t2.y + t3.y;
            }
        }
    }

    float z0 = 0.f, z1 = 0.f, z2 = 0.f, z3 = 0.f;
    #pragma unroll
    for (int j = 0; j < 16; j++) {
        float p = fmaf(psi[j].x, psi[j].x, psi[j].y * psi[j].y);
        z0 += (j & 8) ? -p : p;
        z1 += (j & 4) ? -p : p;
        z2 += (j & 2) ? -p : p;
        z3 += (j & 1) ? -p : p;
    }
    return make_float4(z0, z1, z2, z3);
}

__global__ __launch_bounds__(THREADS, 3)
void qp_fused(const float* __restrict__ x,
              const float* __restrict__ pre_w,
              const float* __restrict__ pre_b,
              const float* __restrict__ qw,
              const float* __restrict__ post_w,
              const float* __restrict__ post_b,
              float4* __restrict__ out4)
{
    __shared__ __align__(16) float wsm[4 * 1024];   // pre_w as stored: [q][1024]
    __shared__ float2 rotm[4][4];
    __shared__ float  pbq[4];
    __shared__ float4 zsm[32];

    const int t = threadIdx.x;
    {
        const float4* src = (const float4*)pre_w;
        float4*       dst = (float4*)wsm;
        #pragma unroll
        for (int i = 0; i < 4; i++) dst[t + THREADS * i] = src[t + THREADS * i];
    }
    if (t < 4) {
        pbq[t] = pre_b[t];
        float phi = qw[t * 3 + 0], th = qw[t * 3 + 1], om = qw[t * 3 + 2];
        float st, ct; sincosf(0.5f * th,         &st, &ct);
        float sp, cp; sincosf(0.5f * (phi + om), &sp, &cp);
        float sm, cm; sincosf(0.5f * (phi - om), &sm, &cm);
        rotm[t][0] = make_float2( ct * cp, -ct * sp);
        rotm[t][1] = make_float2(-st * cm, -st * sm);
        rotm[t][2] = make_float2( st * cm, -st * sm);
        rotm[t][3] = make_float2( ct * cp,  ct * sp);
    }
    __syncthreads();

    const int warp = t >> 5, lane = t & 31;
    const int row0 = blockIdx.x * 32;

    // ---------------- Phase A: h = x @ pre_w.T, 4 rows per warp -----------
    // Packed f32x2 accumulation: per qubit, (even,odd) partial sums in one b64.
    {
        const int rloc = lane >> 3;                // 0..3
        const int cgrp = lane & 7;                 // 0..7
        const int row  = row0 + warp * 4 + rloc;
        const char* xr = (const char*)((const float4*)x + (size_t)row * 256 + cgrp);
        const ulonglong2* w2a = (const ulonglong2*)(wsm)        + cgrp;
        const ulonglong2* w2b = (const ulonglong2*)(wsm + 1024) + cgrp;
        const ulonglong2* w2c = (const ulonglong2*)(wsm + 2048) + cgrp;
        const ulonglong2* w2d = (const ulonglong2*)(wsm + 3072) + cgrp;

        u64 acc0 = 0ull, acc1 = 0ull, acc2 = 0ull, acc3 = 0ull;
        #pragma unroll 8
        for (int i = 0; i < 32; i++) {
            ulonglong2 xv = ldcs_u64x2(xr + (size_t)128 * i);   // float4 = 2x f32x2
            ulonglong2 w0 = w2a[8 * i], w1 = w2b[8 * i], w2 = w2c[8 * i], w3 = w2d[8 * i];
            acc0 = ffma2(xv.x, w0.x, acc0); acc0 = ffma2(xv.y, w0.y, acc0);
            acc1 = ffma2(xv.x, w1.x, acc1); acc1 = ffma2(xv.y, w1.y, acc1);
            acc2 = ffma2(xv.x, w2.x, acc2); acc2 = ffma2(xv.y, w2.y, acc2);
            acc3 = ffma2(xv.x, w3.x, acc3); acc3 = ffma2(xv.y, w3.y, acc3);
        }
        float2 u0 = unpackf2(acc0), u1 = unpackf2(acc1);
        float2 u2 = unpackf2(acc2), u3 = unpackf2(acc3);
        float a0 = u0.x + u0.y, a1 = u1.x + u1.y, a2 = u2.x + u2.y, a3 = u3.x + u3.y;

        // reduce across the 8 lanes of each row group
        #pragma unroll
        for (int off = 1; off < 8; off <<= 1) {
            a0 += __shfl_xor_sync(0xffffffffu, a0, off);
            a1 += __shfl_xor_sync(0xffffffffu, a1, off);
            a2 += __shfl_xor_sync(0xffffffffu, a2, off);
            a3 += __shfl_xor_sync(0xffffffffu, a3, off);
        }

        const float f0 = f_tanh(a0 + pbq[0]) * PI_F;
        const float f1 = f_tanh(a1 + pbq[1]) * PI_F;
        const float f2 = f_tanh(a2 + pbq[2]) * PI_F;
        const float f3 = f_tanh(a3 + pbq[3]) * PI_F;

        float4 z = circuit(f0, f1, f2, f3, rotm);
        if (cgrp == 0) zsm[warp * 4 + rloc] = z;
    }
    __syncthreads();

    // ---------------- Phase B: out = z @ post_w.T + post_b ----------------
    // thread t owns out columns 4t..4t+3; packed over column pairs.
    {
        const float4* pwv = (const float4*)post_w;
        float4 pw0 = pwv[4 * t + 0];
        float4 pw1 = pwv[4 * t + 1];
        float4 pw2 = pwv[4 * t + 2];
        float4 pw3 = pwv[4 * t + 3];
        float4 bv  = ((const float4*)post_b)[t];

        // column-pair packs: P* for (c0,c1), Q* for (c2,c3)
        u64 P0 = packf2(pw0.x, pw1.x), P1 = packf2(pw0.y, pw1.y);
        u64 P2 = packf2(pw0.z, pw1.z), P3 = packf2(pw0.w, pw1.w);
        u64 Q0 = packf2(pw2.x, pw3.x), Q1 = packf2(pw2.y, pw3.y);
        u64 Q2 = packf2(pw2.z, pw3.z), Q3 = packf2(pw2.w, pw3.w);
        u64 B01 = packf2(bv.x, bv.y), B23 = packf2(bv.z, bv.w);

        char* orow = (char*)(out4 + (size_t)row0 * 256 + t);
        #pragma unroll 8
        for (int r = 0; r < 32; r++) {
            float4 zv = zsm[r];
            u64 zx = packf2(zv.x, zv.x), zy = packf2(zv.y, zv.y);
            u64 zz = packf2(zv.z, zv.z), zw = packf2(zv.w, zv.w);
            u64 o01 = ffma2(zx, P0, B01);
            o01 = ffma2(zy, P1, o01);
            o01 = ffma2(zz, P2, o01);
            o01 = ffma2(zw, P3, o01);
            u64 o23 = ffma2(zx, Q0, B23);
            o23 = ffma2(zy, Q1, o23);
            o23 = ffma2(zz, Q2, o23);
            o23 = ffma2(zw, Q3, o23);
            stcs_u64x2(orow + (size_t)4096 * r, o01, o23);
        }
    }
}

extern "C" void kernel_launch(void* const* d_in, const int* in_sizes, int n_in,
                              void* d_out, int out_size)
{
    const float* x      = (const float*)d_in[0];
    const float* pre_w  = (const float*)d_in[1];
    const float* pre_b  = (const float*)d_in[2];
    const float* qw     = (const float*)d_in[3];
    const float* post_w = (const float*)d_in[4];
    const float* post_b = (const float*)d_in[5];
    (void)in_sizes; (void)n_in; (void)out_size;

    qp_fused<<<BLOCKS, THREADS>>>(x, pre_w, pre_b, qw, post_w, post_b, (float4*)d_out);
}